// round 6
// baseline (speedup 1.0000x reference)
#include <cuda_runtime.h>

#define C   32
#define HF  96
#define WF  192
#define DD  192
#define HOUT 384
#define WOUT 768
#define ND  48
#define CHW (HF*WF)
#define COST_ELEMS (DD*HF*WF)
#define TP  (WF + 16)          // padded t row: 16 zero floats before index 0

// ---- packed f32x2 helpers (sm_103a) ----------------------------------------
__device__ __forceinline__ unsigned long long pack2(float lo, float hi) {
    unsigned long long r;
    asm("mov.b64 %0, {%1, %2};" : "=l"(r) : "f"(lo), "f"(hi));
    return r;
}
__device__ __forceinline__ void fma2(unsigned long long& acc,
                                     unsigned long long a, unsigned long long b) {
    asm("fma.rn.f32x2 %0, %1, %2, %0;" : "+l"(acc) : "l"(a), "l"(b));
}
__device__ __forceinline__ float2 unpack2(unsigned long long v) {
    float lo, hi;
    asm("mov.b64 {%0, %1}, %2;" : "=f"(lo), "=f"(hi) : "l"(v));
    return make_float2(lo, hi);
}

// ---------------------------------------------------------------------------
// Kernel 1: normalized cosine cost volume. ONE WAVE: grid (48 h-pairs, 3),
// 768 threads, ~100KB dynamic smem. Each thread computes one 4w x 8d tile
// with LDS.128 operand loads and packed fma.rn.f32x2 accumulation (halves
// fma-pipe issue). Zero-padded t rows keep one branch-free code path.
// cost[d,h,w] = sum_c rn[c,w]*tn[c,w-d], exactly 0 for w<d.
// ---------------------------------------------------------------------------
__global__ __launch_bounds__(768) void cost_kernel(
    const float* __restrict__ ref, const float* __restrict__ tgt,
    float* __restrict__ out)
{
    extern __shared__ float smbuf[];
    float (*r)[C][WF] = reinterpret_cast<float (*)[C][WF]>(smbuf);
    float (*t)[C][TP] = reinterpret_cast<float (*)[C][TP]>(smbuf + 2*C*WF);

    const int hp  = blockIdx.x;          // h-pair 0..47
    const int by  = blockIdx.y;          // 0..2
    const int tid = threadIdx.x;         // 0..767
    const int hrow0 = hp * 2;

    // zero the 2*C*16 pad floats
    if (tid < 2*C*4) {
        int row = tid / (C*4);
        int c   = (tid / 4) % C;
        int q   = tid % 4;
        *reinterpret_cast<float4*>(&t[row][c][q*4]) = make_float4(0.f,0.f,0.f,0.f);
    }

    // vectorized loads: 3072 float4 per tensor (2 rows x 32 c x 48 quads)
    #pragma unroll
    for (int j = 0; j < 4; j++) {
        int k   = tid + j*768;
        int c   = k / 48;
        int kk  = k % 48;
        int row = c / C;
        int cc  = c % C;
        *reinterpret_cast<float4*>(&r[row][cc][kk*4]) =
            *reinterpret_cast<const float4*>(ref + cc*CHW + (hrow0+row)*WF + kk*4);
        *reinterpret_cast<float4*>(&t[row][cc][16 + kk*4]) =
            *reinterpret_cast<const float4*>(tgt + cc*CHW + (hrow0+row)*WF + kk*4);
    }
    __syncthreads();

    // per-pixel channel normalization: 384 columns (2 rows x 192 w)
    if (tid < 2*WF) {
        int row = tid / WF;
        int w   = tid % WF;
        float sr = 0.f, st = 0.f;
        #pragma unroll
        for (int c = 0; c < C; c++) {
            float a = r[row][c][w];      sr = fmaf(a, a, sr);
            float b = t[row][c][16 + w]; st = fmaf(b, b, st);
        }
        float ir  = rsqrtf(sr + 1e-12f);
        float itv = rsqrtf(st + 1e-12f);
        #pragma unroll
        for (int c = 0; c < C; c++) { r[row][c][w] *= ir; t[row][c][16 + w] *= itv; }
    }
    __syncthreads();

    // one 4w x 8d tile per thread
    const int hr = (tid >= 384) ? 1 : 0;
    const int tm = tid - hr*384;
    const int wq = tm % 48;
    const int dq = tm / 48;
    const int w0 = wq * 4;
    const int d0 = 8 * (3*dq + by);
    const int h  = hrow0 + hr;

    unsigned long long axy0[8], azw0[8];   // (acc.x,acc.y) / (acc.z,acc.w) per i
    #pragma unroll
    for (int i = 0; i < 8; i++) { axy0[i] = 0ULL; azw0[i] = 0ULL; }

    const int pb = 16 + w0 - d0 - 8;       // padded window base (mult of 4)

    if (w0 - d0 >= 0) {
        #pragma unroll
        for (int c = 0; c < C; c++) {
            float4 a  = *reinterpret_cast<const float4*>(&r[hr][c][w0]);
            float4 v0 = *reinterpret_cast<const float4*>(&t[hr][c][pb]);
            float4 v1 = *reinterpret_cast<const float4*>(&t[hr][c][pb + 4]);
            float4 v2 = *reinterpret_cast<const float4*>(&t[hr][c][pb + 8]);
            float e[12] = {v0.x, v0.y, v0.z, v0.w,
                           v1.x, v1.y, v1.z, v1.w,
                           v2.x, v2.y, v2.z, v2.w};
            unsigned long long pxy = pack2(a.x, a.y);
            unsigned long long pzw = pack2(a.z, a.w);
            // P[j] = (e[j], e[j+1]); xy uses P[8-i], zw uses P[10-i]
            #pragma unroll
            for (int j = 1; j <= 10; j++) {
                unsigned long long P = pack2(e[j], e[j+1]);
                if (j <= 8) fma2(axy0[8 - j], pxy, P);
                if (j >= 3) fma2(azw0[10 - j], pzw, P);
            }
        }
    }
    // w0 < d0: entire tile is w < d -> exact zeros

    #pragma unroll
    for (int i = 0; i < 8; i++) {
        float2 xy = unpack2(axy0[i]);
        float2 zw = unpack2(azw0[i]);
        float4 o = make_float4(xy.x, xy.y, zw.x, zw.y);
        *reinterpret_cast<float4*>(&out[((d0 + i)*HF + h)*WF + w0]) = o;
    }
}

// ---------------------------------------------------------------------------
// Kernel 2: fused trilinear upsample + argmax + clamp(.,1).
// Factored interpolation: cooperative h-lerp into hcol[ty][wc][d], then each
// thread only w-lerps. Candidate scan in x8-scaled domain (exact, order-
// preserving): cand(e) = 7*s[e] + max(s[e-1], s[e+1]); exact-sample
// candidates 8*s[0] (k=0) and 8*s[47] (k=190). First-occurrence ties kept.
// ---------------------------------------------------------------------------
#define SSTR 52

__device__ __forceinline__ void chunk8h(const float* __restrict__ hA,
                                        const float* __restrict__ hB,
                                        int dbase, float fw,
                                        float* __restrict__ s)
{
    #pragma unroll
    for (int half = 0; half < 2; half++) {
        float4 u = *reinterpret_cast<const float4*>(hA + dbase + half*4);
        float4 v = *reinterpret_cast<const float4*>(hB + dbase + half*4);
        s[half*4+0] = fmaf(fw, v.x - u.x, u.x);
        s[half*4+1] = fmaf(fw, v.y - u.y, u.y);
        s[half*4+2] = fmaf(fw, v.z - u.z, u.z);
        s[half*4+3] = fmaf(fw, v.w - u.w, u.w);
    }
}

__device__ __forceinline__ float wlerp1(const float* __restrict__ hA,
                                        const float* __restrict__ hB,
                                        int d, float fw)
{
    return fmaf(fw, hB[d] - hA[d], hA[d]);
}

__device__ __forceinline__ void scan_head(const float* __restrict__ s,
                                          float& best, int& bestE)
{
    #pragma unroll
    for (int e = 0; e < 7; e++) {
        float nb = (e == 0) ? s[1] : fmaxf(s[e-1], s[e+1]);
        float cand = fmaf(7.0f, s[e], nb);
        if (cand > best) { best = cand; bestE = e; }
    }
}

__device__ __forceinline__ void scan_mid(const float* __restrict__ p,
                                         const float* __restrict__ c,
                                         int qb, float& best, int& bestE)
{
    {   float nb = fmaxf(p[6], c[0]);
        float cand = fmaf(7.0f, p[7], nb);
        if (cand > best) { best = cand; bestE = qb - 1; } }
    {   float nb = fmaxf(p[7], c[1]);
        float cand = fmaf(7.0f, c[0], nb);
        if (cand > best) { best = cand; bestE = qb; } }
    #pragma unroll
    for (int j = 1; j < 7; j++) {
        float nb = fmaxf(c[j-1], c[j+1]);
        float cand = fmaf(7.0f, c[j], nb);
        if (cand > best) { best = cand; bestE = qb + j; }
    }
}

__global__ __launch_bounds__(256) void pred_kernel(
    const float* __restrict__ cost, float* __restrict__ pred)
{
    __shared__ float sc[4][10][SSTR];    // raw cost rows
    __shared__ float hcol[8][10][SSTR];  // h-lerped per output row ty
    const int tx = threadIdx.x, ty = threadIdx.y;
    const int tid = ty*32 + tx;
    const int hb = 2*(int)blockIdx.y - 1;
    const int wb = 8*(int)blockIdx.x - 1;

    #pragma unroll
    for (int it = 0; it < 8; it++) {
        int i = tid + it * 256;
        if (i < 4*10*ND) {
            int wc = i % 10;
            int hr = (i / 10) % 4;
            int d  = i / 40;
            int hh = min(max(hb + hr, 0), HF - 1);
            int ww = min(max(wb + wc, 0), WF - 1);
            sc[hr][wc][d] = cost[(d*HF + hh)*WF + ww];
        }
    }
    __syncthreads();

    // cooperative h-lerp: 8 ty x 10 wc x 12 dquads = 960 float4 lerps
    #pragma unroll
    for (int it = 0; it < 4; it++) {
        int i = tid + it * 256;
        if (i < 960) {
            int ty2 = i / 120;
            int rem = i % 120;
            int wc  = rem / 12;
            int q   = rem % 12;
            int ho2 = (int)blockIdx.y*8 + ty2;
            float xh2 = fminf(fmaxf(0.25f*(float)ho2 - 0.375f, 0.f), (float)(HF-1));
            int h02 = min((int)xh2, HF - 2);
            float fh2 = xh2 - (float)h02;
            int lh2 = h02 - hb;
            float4 u = *reinterpret_cast<const float4*>(&sc[lh2][wc][q*4]);
            float4 v = *reinterpret_cast<const float4*>(&sc[lh2+1][wc][q*4]);
            float4 o;
            o.x = fmaf(fh2, v.x - u.x, u.x);
            o.y = fmaf(fh2, v.y - u.y, u.y);
            o.z = fmaf(fh2, v.z - u.z, u.z);
            o.w = fmaf(fh2, v.w - u.w, u.w);
            *reinterpret_cast<float4*>(&hcol[ty2][wc][q*4]) = o;
        }
    }
    __syncthreads();

    const int wo = blockIdx.x*32 + tx;
    const int ho = blockIdx.y*8 + ty;

    float xw = fminf(fmaxf(0.25f*(float)wo - 0.375f, 0.f), (float)(WF - 1));
    int   w0 = min((int)xw, WF - 2);
    float fw = xw - (float)w0;
    const int lw = w0 - wb;

    const float* hA = &hcol[ty][lw][0];
    const float* hB = &hcol[ty][lw+1][0];

    float sA[8], sB[8];
    float best;
    int bestE = -1;                      // -1 => k = 0

    chunk8h(hA, hB, 0, fw, sA);
    best = 8.0f * sA[0];                 // exact sample s[0] (scaled)
    scan_head(sA, best, bestE);

    chunk8h(hA, hB,  8, fw, sB); scan_mid(sA, sB,  8, best, bestE);
    chunk8h(hA, hB, 16, fw, sA); scan_mid(sB, sA, 16, best, bestE);
    chunk8h(hA, hB, 24, fw, sB); scan_mid(sA, sB, 24, best, bestE);
    chunk8h(hA, hB, 32, fw, sA); scan_mid(sB, sA, 32, best, bestE);
    chunk8h(hA, hB, 40, fw, sB); scan_mid(sA, sB, 40, best, bestE);

    {   // e = 47
        float nb = sB[6];
        float cand = fmaf(7.0f, sB[7], nb);
        if (cand > best) { best = cand; bestE = 47; }
    }
    float s47 = sB[7];

    int k;
    if (8.0f * s47 > best) {
        k = 4*(ND-1) + 2;                   // 190: exact sample s[47]
    } else if (bestE < 0) {
        k = 0;
    } else {
        float smL = -3.0e38f, smR = -3.0e38f;
        if (bestE > 0)      smL = wlerp1(hA, hB, bestE - 1, fw);
        if (bestE < ND - 1) smR = wlerp1(hA, hB, bestE + 1, fw);
        k = 4*bestE + 1 + ((smR > smL) ? 1 : 0);   // tie -> left (smaller k)
    }
    k = max(k, 1);
    pred[ho*WOUT + wo] = (float)k;
}

// ---------------------------------------------------------------------------
extern "C" void kernel_launch(void* const* d_in, const int* in_sizes, int n_in,
                              void* d_out, int out_size)
{
    const float* left  = (const float*)d_in[0];
    const float* right = (const float*)d_in[1];
    float* out = (float*)d_out;

    const int smem_bytes = (2*C*WF + 2*C*TP) * (int)sizeof(float);  // 100 KB
    cudaFuncSetAttribute(cost_kernel,
                         cudaFuncAttributeMaxDynamicSharedMemorySize, smem_bytes);

    dim3 g1(HF/2, 3), b1(768);
    cost_kernel<<<g1, b1, smem_bytes>>>(left, right, out);

    dim3 g2(WOUT/32, HOUT/8), b2(32, 8);
    pred_kernel<<<g2, b2>>>(out, out + COST_ELEMS);
}